// round 2
// baseline (speedup 1.0000x reference)
#include <cuda_runtime.h>

// Problem constants
#define NCARDS 50000
#define NJ 49999          // columns of adj / similarities (cards 1..49999)
#define B 1024
#define D 64
#define H 256
#define JT 19             // j-tiles (grid.x)
#define CHUNK 2688        // columns per j-tile block (21 inner tiles of 128)
#define NJ_PAD (JT*CHUNK) // 51072
#define TILES 21
#define LOG2E 1.4426950408889634f
#define LN2F  0.6931471805599453f
#define KL_EPS 1e-7f
#define LN_EPS  -16.118095650958319f   // ln(1e-7)
#define LG2_EPS -23.253496664211536f   // log2(1e-7)

// ---------------- device scratch (static, no allocation) ----------------
__device__ float g_eT[(size_t)D*NJ_PAD];   // normalized embeddings, transposed [k][j], zero-padded
__device__ float g_aT[D*B];                // t * normalized MLP output, transposed [k][b]
__device__ float g_pm[JT*B], g_pz[JT*B], g_pt1[JT*B], g_pt2[JT*B], g_pt3[JT*B], g_ps[JT*B];
__device__ float g_cross[B], g_t3[B], g_lse[B];
__device__ int   g_flag[B];

// ---------------- helpers ----------------
__device__ __forceinline__ float ex2f_(float x){ float r; asm("ex2.approx.f32 %0, %1;" : "=f"(r) : "f"(x)); return r; }
__device__ __forceinline__ float lg2f_(float x){ float r; asm("lg2.approx.f32 %0, %1;" : "=f"(r) : "f"(x)); return r; }
__device__ __forceinline__ unsigned long long pack2_(float lo, float hi){
    unsigned long long r; asm("mov.b64 %0, {%1, %2};" : "=l"(r) : "f"(lo), "f"(hi)); return r; }
__device__ __forceinline__ void unpack2_(unsigned long long v, float& lo, float& hi){
    asm("mov.b64 {%0, %1}, %2;" : "=f"(lo), "=f"(hi) : "l"(v)); }
#define FMA2(d,a,b) asm("fma.rn.f32x2 %0, %1, %2, %0;" : "+l"(d) : "l"(a), "l"(b))

// ---------------- kernel 1: normalize embeddings[1:], transpose, pad with zeros ----------------
__global__ void k_enorm(const float* __restrict__ emb){
    __shared__ float sm[64][65];
    __shared__ float inv[64];
    int tid = threadIdx.x;
    int jbase = blockIdx.x * 64;
#pragma unroll
    for(int i=0;i<16;i++){
        int idx = tid + i*256;
        int c = idx >> 6, k = idx & 63;
        int j = jbase + c;
        sm[c][k] = (j < NJ) ? emb[(size_t)(j+1)*D + k] : 0.0f;
    }
    __syncthreads();
    if(tid < 64){
        float s = 0.f;
#pragma unroll
        for(int k=0;k<64;k++){ float v = sm[tid][k]; s += v*v; }
        inv[tid] = rsqrtf(fmaxf(s, 1e-12f));
    }
    __syncthreads();
#pragma unroll
    for(int i=0;i<16;i++){
        int idx = tid + i*256;
        int k = idx >> 6, c = idx & 63;
        g_eT[(size_t)k*NJ_PAD + jbase + c] = sm[c][k] * inv[c];
    }
}

// ---------------- kernel 2: gather + MLP + l2norm + temperature fold ----------------
__global__ void k_mlp(const int* __restrict__ cards, const float* __restrict__ emb,
                      const float* __restrict__ W1, const float* __restrict__ b1,
                      const float* __restrict__ W2, const float* __restrict__ b2,
                      const float* __restrict__ temp){
    __shared__ float se[64];
    __shared__ float sh[256];
    __shared__ float so[64];
    __shared__ float red[64];
    int b = blockIdx.x, t = threadIdx.x;
    if(t < 64){ int c = cards[b]; se[t] = emb[(size_t)c*D + t]; }
    __syncthreads();
    float h = b1[t];
#pragma unroll
    for(int k=0;k<64;k++) h += se[k] * W1[k*256 + t];
    sh[t] = fmaxf(h, 0.0f);
    __syncthreads();
    if(t < 64){
        float o = b2[t];
#pragma unroll 8
        for(int j=0;j<256;j++) o += sh[j] * W2[j*64 + t];
        so[t] = o;
        red[t] = o*o;
    }
    __syncthreads();
    for(int s=32;s>0;s>>=1){ if(t < s) red[t] += red[t+s]; __syncthreads(); }
    if(t < 64){
        float scale = temp[0] * rsqrtf(fmaxf(red[0], 1e-12f));
        g_aT[t*B + b] = so[t] * scale;   // logits l = dot(aT, eT) = t * cos_sim
    }
}

// ---------------- kernel 3: fused GEMM + online softmax stats + adj cross-stats ----------------
// grid (JT, 8), 256 threads, dynamic smem 64KB
extern "C" __global__ void __launch_bounds__(256)
k_gemm(const float* __restrict__ adj){
    extern __shared__ float smem[];
    float* As = smem;            // [64][128]
    float* Es = smem + 64*128;   // [64][128]
    int tid = threadIdx.x;
    int tx = tid & 15, ty = tid >> 4;
    int jt = blockIdx.x, rt = blockIdx.y;
    int jstart = jt * CHUNK;

    // load A tile once (already transposed: [k][row])
#pragma unroll
    for(int i=0;i<8;i++){
        int idx4 = tid + i*256;
        int k = idx4 >> 5; int c4 = (idx4 & 31) * 4;
        *(float4*)&As[k*128 + c4] = *(const float4*)&g_aT[k*B + rt*128 + c4];
    }

    float m[8], z[8], t1[8], t2[8], t3[8], smin[8];
#pragma unroll
    for(int i=0;i<8;i++){ m[i]=-INFINITY; z[i]=0.f; t1[i]=0.f; t2[i]=0.f; t3[i]=0.f; smin[i]=INFINITY; }

    int nvalid = NJ - jstart;
    int ntiles = (nvalid + 127) >> 7; if(ntiles > TILES) ntiles = TILES;

    for(int t=0;t<ntiles;t++){
        int j0 = jstart + (t << 7);
        float4 ld[8];
#pragma unroll
        for(int i=0;i<8;i++){
            int idx4 = tid + i*256;
            int k = idx4 >> 5; int c4 = (idx4 & 31) * 4;
            ld[i] = *(const float4*)&g_eT[(size_t)k*NJ_PAD + j0 + c4];
        }
        __syncthreads();
#pragma unroll
        for(int i=0;i<8;i++){
            int idx4 = tid + i*256;
            int k = idx4 >> 5; int c4 = (idx4 & 31) * 4;
            *(float4*)&Es[k*128 + c4] = ld[i];
        }
        __syncthreads();

        unsigned long long acc[8][4];
#pragma unroll
        for(int i=0;i<8;i++)
#pragma unroll
            for(int p=0;p<4;p++) acc[i][p] = 0ull;

#pragma unroll 8
        for(int k=0;k<64;k++){
            float4 a0 = *(const float4*)&As[k*128 + ty*8];
            float4 a1 = *(const float4*)&As[k*128 + ty*8 + 4];
            ulonglong2 bv0 = *(const ulonglong2*)&Es[k*128 + tx*4];
            ulonglong2 bv1 = *(const ulonglong2*)&Es[k*128 + 64 + tx*4];
            float av[8] = {a0.x,a0.y,a0.z,a0.w,a1.x,a1.y,a1.z,a1.w};
#pragma unroll
            for(int i=0;i<8;i++){
                unsigned long long aa = pack2_(av[i], av[i]);
                FMA2(acc[i][0], aa, bv0.x);
                FMA2(acc[i][1], aa, bv0.y);
                FMA2(acc[i][2], aa, bv1.x);
                FMA2(acc[i][3], aa, bv1.y);
            }
        }

        // fused epilogue: online softmax stats + adj cross-stats
        bool full = (j0 + 128) <= NJ;
#pragma unroll
        for(int i=0;i<8;i++){
            float l[8], y[8], le[8], lf[8];
            unpack2_(acc[i][0], l[0], l[1]);
            unpack2_(acc[i][1], l[2], l[3]);
            unpack2_(acc[i][2], l[4], l[5]);
            unpack2_(acc[i][3], l[6], l[7]);
            int brow = rt*128 + ty*8 + i;
            const float* arow = adj + (size_t)brow*NJ + j0;
            if(full){
#pragma unroll
                for(int c=0;c<4;c++){
                    y[c]   = __ldcs(arow + tx*4 + c);
                    y[c+4] = __ldcs(arow + 64 + tx*4 + c);
                }
#pragma unroll
                for(int c=0;c<8;c++){ y[c] = fminf(fmaxf(y[c], KL_EPS), 1.0f); le[c] = l[c]; lf[c] = l[c]; }
            } else {
#pragma unroll
                for(int c=0;c<8;c++){
                    int off = (c < 4) ? (tx*4 + c) : (64 + tx*4 + (c - 4));
                    bool v = (j0 + off) < NJ;
                    float a = v ? __ldcs(arow + off) : 0.0f;
                    y[c]  = v ? fminf(fmaxf(a, KL_EPS), 1.0f) : 0.0f;
                    le[c] = v ? l[c] : -INFINITY;
                    lf[c] = v ? l[c] :  INFINITY;
                }
            }
            float lmax = le[0], lmin = lf[0];
#pragma unroll
            for(int c=1;c<8;c++){ lmax = fmaxf(lmax, le[c]); lmin = fminf(lmin, lf[c]); }
            float mn = fmaxf(m[i], lmax);
            float zn = z[i] * ex2f_((m[i]-mn)*LOG2E);
#pragma unroll
            for(int c=0;c<8;c++) zn += ex2f_((le[c]-mn)*LOG2E);
            z[i] = zn; m[i] = mn;
            float s1=0.f, s2=0.f, s3=0.f;
#pragma unroll
            for(int c=0;c<8;c++){
                s1 += y[c]*l[c];
                s2 += y[c];
                s3 += y[c]*lg2f_(fmaxf(y[c], KL_EPS));
            }
            t1[i] += s1; t2[i] += s2; t3[i] += s3;
            smin[i] = fminf(smin[i], lmin);
        }
    }

    // reduce across tx (lanes 0..15 within each half-warp)
#pragma unroll
    for(int i=0;i<8;i++){
#pragma unroll
        for(int off=8; off>0; off>>=1){
            float mo = __shfl_xor_sync(0xffffffffu, m[i], off);
            float zo = __shfl_xor_sync(0xffffffffu, z[i], off);
            float mn = fmaxf(m[i], mo);
            z[i] = z[i]*ex2f_((m[i]-mn)*LOG2E) + zo*ex2f_((mo-mn)*LOG2E);
            m[i] = mn;
            t1[i] += __shfl_xor_sync(0xffffffffu, t1[i], off);
            t2[i] += __shfl_xor_sync(0xffffffffu, t2[i], off);
            t3[i] += __shfl_xor_sync(0xffffffffu, t3[i], off);
            smin[i] = fminf(smin[i], __shfl_xor_sync(0xffffffffu, smin[i], off));
        }
        if(tx == 0){
            int brow = rt*128 + ty*8 + i;
            int o = jt*B + brow;
            g_pm[o]=m[i]; g_pz[o]=z[i]; g_pt1[o]=t1[i]; g_pt2[o]=t2[i]; g_pt3[o]=t3[i]; g_ps[o]=smin[i];
        }
    }
}

// ---------------- kernel 4: per-row merge of j-tile partials ----------------
__global__ void k_rowred(){
    int b = threadIdx.x;
    float M=-INFINITY, Z=0.f, T1=0.f, T2=0.f, T3=0.f, S=INFINITY;
    for(int jt=0;jt<JT;jt++){
        int o = jt*B + b;
        float mo = g_pm[o], zo = g_pz[o];
        float mn = fmaxf(M, mo);
        Z = Z*ex2f_((M-mn)*LOG2E) + zo*ex2f_((mo-mn)*LOG2E);
        M = mn;
        T1 += g_pt1[o]; T2 += g_pt2[o]; T3 += g_pt3[o];
        S = fminf(S, g_ps[o]);
    }
    float lse = M + lg2f_(Z)*LN2F;          // natural-log LSE of logits
    g_lse[b]  = lse;
    g_t3[b]   = T3;                          // sum y*log2(y)
    g_cross[b] = (T1 - lse*T2)*LOG2E;        // sum y*log2(p) (no clip)
    g_flag[b] = ((S - lse) < LN_EPS) ? 1 : 0;
}

// ---------------- kernel 5: exact clipped recompute (rare/never taken) ----------------
__global__ void k_fixup(const float* __restrict__ adj){
    int b = blockIdx.x;
    if(!g_flag[b]) return;
    __shared__ float a[64];
    __shared__ float red[256];
    int t = threadIdx.x;
    if(t < 64) a[t] = g_aT[t*B + b];
    __syncthreads();
    float lse = g_lse[b];
    float cr = 0.f;
    for(int j=t; j<NJ; j+=256){
        float l = 0.f;
#pragma unroll
        for(int k=0;k<64;k++) l += a[k]*g_eT[(size_t)k*NJ_PAD + j];
        float y = fminf(fmaxf(adj[(size_t)b*NJ + j], KL_EPS), 1.0f);
        cr += y * fmaxf((l - lse)*LOG2E, LG2_EPS);
    }
    red[t] = cr; __syncthreads();
    for(int s=128;s>0;s>>=1){ if(t < s) red[t] += red[t+s]; __syncthreads(); }
    if(t == 0) g_cross[b] = red[0];
}

// ---------------- kernel 6: final loss ----------------
__global__ void k_loss(const float* __restrict__ temp, float* __restrict__ out){
    __shared__ float red[B];
    int t = threadIdx.x;
    red[t] = g_t3[t] - g_cross[t];           // KL in bits, per row
    __syncthreads();
    for(int s=512;s>0;s>>=1){ if(t < s) red[t] += red[t+s]; __syncthreads(); }
    if(t == 0){
        float T = temp[0];
        out[0] = red[0]*(1.0f/(float)B) + T*T*0.01f;
    }
}

// ---------------- launch ----------------
extern "C" void kernel_launch(void* const* d_in, const int* in_sizes, int n_in,
                              void* d_out, int out_size){
    const int*   cards = (const int*)  d_in[0];
    const float* adj   = (const float*)d_in[1];
    const float* emb   = (const float*)d_in[2];
    const float* W1    = (const float*)d_in[3];
    const float* b1    = (const float*)d_in[4];
    const float* W2    = (const float*)d_in[5];
    const float* b2    = (const float*)d_in[6];
    const float* temp  = (const float*)d_in[7];

    cudaFuncSetAttribute(k_gemm, cudaFuncAttributeMaxDynamicSharedMemorySize, 65536);

    k_enorm<<<NJ_PAD/64, 256>>>(emb);
    k_mlp<<<B, 256>>>(cards, emb, W1, b1, W2, b2, temp);
    k_gemm<<<dim3(JT, 8), 256, 65536>>>(adj);
    k_rowred<<<1, B>>>();
    k_fixup<<<B, 256>>>(adj);
    k_loss<<<1, B>>>(temp, (float*)d_out);
}

// round 4
// speedup vs baseline: 2.2077x; 2.2077x over previous
#include <cuda_runtime.h>
#include <cuda_bf16.h>
#include <cstdint>

#define NCARDS 50000
#define NJ 49999
#define B 1024
#define JT 19
#define CHUNK 2688
#define NJ_PAD (JT*CHUNK)   // 51072
#define TILES 21
#define LOG2E 1.4426950408889634f
#define KL_EPS 1e-7f
#define LG2_EPS -23.253496664211536f   // log2(1e-7)

// smem layout for k_gemm3 (bytes)
#define ES_STRIDE 144               // padded E row (conflict-free B loads)
#define ES_BYTES  (128*ES_STRIDE)   // 18432
#define ADJ_PITCH 130               // floats per sadj row (even -> float2 aligned)
#define ADJ_BYTES (128*ADJ_PITCH*4) // 66560
#define SMEM_TOTAL3 (2*ES_BYTES + 2*ADJ_BYTES)  // 169984

// ---------------- device scratch ----------------
__device__ __nv_bfloat16 g_eB[(size_t)NJ_PAD*64];  // normalized E, [j][k] row-major bf16, zero-padded
__device__ __nv_bfloat16 g_aBF[B*64];              // (t*log2e)*normalized MLP out, [b][k] bf16
__device__ float g_pz[JT*B], g_pt1[JT*B], g_pt2[JT*B], g_pt3[JT*B], g_ps[JT*B];
__device__ float g_cross[B], g_t3v[B], g_lse2[B];
__device__ int   g_flag[B];

// ---------------- helpers ----------------
__device__ __forceinline__ float ex2f_(float x){ float r; asm("ex2.approx.f32 %0, %1;" : "=f"(r) : "f"(x)); return r; }
__device__ __forceinline__ float lg2f_(float x){ float r; asm("lg2.approx.f32 %0, %1;" : "=f"(r) : "f"(x)); return r; }
__device__ __forceinline__ uint32_t smem_u32(const void* p){
    uint32_t a; asm("{ .reg .u64 t; cvta.to.shared.u64 t, %1; cvt.u32.u64 %0, t; }" : "=r"(a) : "l"(p)); return a; }

__device__ __forceinline__ void mma16816(float* c, const uint32_t* a, uint32_t b0, uint32_t b1){
    asm volatile("mma.sync.aligned.m16n8k16.row.col.f32.bf16.bf16.f32 "
        "{%0,%1,%2,%3}, {%4,%5,%6,%7}, {%8,%9}, {%0,%1,%2,%3};"
        : "+f"(c[0]), "+f"(c[1]), "+f"(c[2]), "+f"(c[3])
        : "r"(a[0]), "r"(a[1]), "r"(a[2]), "r"(a[3]), "r"(b0), "r"(b1));
}

__device__ __forceinline__ void upd(float L, float y, float& z, float& t1, float& t2, float& t3, float& mn){
    y = fminf(fmaxf(y, KL_EPS), 1.0f);
    z += ex2f_(L);
    t1 = fmaf(y, L, t1);
    t2 += y;
    t3 = fmaf(y, lg2f_(y), t3);
    mn = fminf(mn, L);
}

// ---------------- kernel 1: normalize E[1:], write bf16 [j][k], zero-pad ----------------
__global__ void k_enorm(const float* __restrict__ emb){
    int wid = threadIdx.x>>5, lane = threadIdx.x&31;
    int j = blockIdx.x*8 + wid;
    float2 v = make_float2(0.f, 0.f);
    if (j < NJ) v = ((const float2*)emb)[(size_t)(j+1)*32 + lane];
    float s = v.x*v.x + v.y*v.y;
#pragma unroll
    for(int o=16;o;o>>=1) s += __shfl_xor_sync(0xffffffffu, s, o);
    float inv = rsqrtf(fmaxf(s, 1e-12f));
    __nv_bfloat162 o2;
    o2.x = __float2bfloat16_rn(v.x*inv);
    o2.y = __float2bfloat16_rn(v.y*inv);
    ((__nv_bfloat162*)g_eB)[(size_t)j*32 + lane] = o2;
}

// ---------------- kernel 2: gather + MLP + l2norm, fold t*log2e, write bf16 ----------------
__global__ void __launch_bounds__(256) k_mlp(const int* __restrict__ cards, const float* __restrict__ emb,
        const float* __restrict__ W1, const float* __restrict__ b1,
        const float* __restrict__ W2, const float* __restrict__ b2,
        const float* __restrict__ temp){
    extern __shared__ float dyn[];
    float* sW1 = dyn;              // 16384
    float* sW2 = dyn + 16384;      // 16384
    float* se  = dyn + 32768;      // 1024
    float* sh  = dyn + 33792;      // 4096
    float* so  = dyn + 37888;      // 1024
    float* ssc = dyn + 38912;      // 16
    int t = threadIdx.x;
    int b0 = blockIdx.x*16;
    const float4* W1v = (const float4*)W1; float4* s1v = (float4*)sW1;
    const float4* W2v = (const float4*)W2; float4* s2v = (float4*)sW2;
#pragma unroll
    for(int i=0;i<16;i++) s1v[t + i*256] = W1v[t + i*256];
#pragma unroll
    for(int i=0;i<16;i++) s2v[t + i*256] = W2v[t + i*256];
#pragma unroll
    for(int i=0;i<4;i++){ int idx = t + i*256; int bi = idx>>6, k = idx&63;
        se[idx] = emb[(size_t)cards[b0+bi]*64 + k]; }
    __syncthreads();
    float bb1 = b1[t];
    for(int bi=0;bi<16;bi++){
        float h = bb1;
#pragma unroll
        for(int k=0;k<64;k++) h = fmaf(se[bi*64+k], sW1[k*256+t], h);
        sh[bi*256+t] = fmaxf(h, 0.f);
    }
    __syncthreads();
    int d = t&63, g = t>>6;
    float bb2 = b2[d];
    for(int r=0;r<4;r++){
        int bi = g*4 + r;
        float o = bb2;
#pragma unroll 8
        for(int j=0;j<256;j++) o = fmaf(sh[bi*256+j], sW2[j*64+d], o);
        so[bi*64+d] = o;
    }
    __syncthreads();
    if (t < 16){
        float s = 0.f;
#pragma unroll
        for(int dd=0;dd<64;dd++){ float v = so[t*64+dd]; s = fmaf(v, v, s); }
        ssc[t] = temp[0]*LOG2E*rsqrtf(fmaxf(s, 1e-12f));
    }
    __syncthreads();
#pragma unroll
    for(int i=0;i<4;i++){ int idx = t + i*256; int bi = idx>>6;
        g_aBF[(size_t)b0*64 + idx] = __float2bfloat16_rn(so[idx]*ssc[bi]); }
}

// ---------------- staging for k_gemm3 ----------------
__device__ __forceinline__ void stage_tile(int buf, int j0, int jv, const float* __restrict__ adj,
                                           int rt, uint32_t smbase, int tid){
    uint32_t eb = smbase + buf*ES_BYTES;
    uint32_t ab = smbase + 2*ES_BYTES + buf*ADJ_BYTES;
    // E tile: 128 rows x 128B, 16B cp.async (dst rows padded to 144B, 144 = 9*16)
#pragma unroll
    for(int i=0;i<4;i++){
        int c = tid + i*256;
        int row = c>>3, seg = c&7;
        uint32_t dst = eb + row*ES_STRIDE + seg*16;
        const char* src = (const char*)g_eB + (size_t)(j0+row)*128 + seg*16;
        asm volatile("cp.async.cg.shared.global [%0], [%1], 16;" :: "r"(dst), "l"(src));
    }
    if (jv == 128){
#pragma unroll
        for(int i=0;i<64;i++){
            int idx = tid + i*256;
            int row = idx>>7, col = idx&127;
            uint32_t dst = ab + (uint32_t)(row*ADJ_PITCH + col)*4u;
            const float* src = adj + (size_t)(rt*128+row)*NJ + j0 + col;
            asm volatile("cp.async.ca.shared.global [%0], [%1], 4;" :: "r"(dst), "l"(src));
        }
    } else {
        for(int i=0;i<64;i++){
            int idx = tid + i*256;
            int row = idx>>7, col = idx&127;
            float v = 0.f;
            if (col < jv) v = __ldcs(adj + (size_t)(rt*128+row)*NJ + j0 + col);
            uint32_t dst = ab + (uint32_t)(row*ADJ_PITCH + col)*4u;
            asm volatile("st.shared.f32 [%0], %1;" :: "r"(dst), "f"(v));
        }
    }
    asm volatile("cp.async.commit_group;" ::: "memory");
}

// ---------------- kernel 3: HMMA GEMM + fused stats ----------------
// grid (19, 8), 256 threads (8 warps x 16 rows). Logits in log2 domain.
__global__ void __launch_bounds__(256) k_gemm3(const float* __restrict__ adj){
    extern __shared__ __align__(16) char sm3[];
    const uint32_t smbase = smem_u32(sm3);
    int tid = threadIdx.x;
    int wid = tid>>5, lane = tid&31, g = lane>>2, tg = lane&3;
    int jt = blockIdx.x, rt = blockIdx.y;
    int jstart = jt*CHUNK;
    int nvalid = NJ - jstart;
    int ntiles = (nvalid + 127)>>7; if (ntiles > TILES) ntiles = TILES;

    // A fragments (constant over j-tiles): rows wid*16+g and +8, all 4 k-tiles
    uint32_t A[4][4];
    {
        int r0 = rt*128 + wid*16 + g;
        const uint32_t* a0 = (const uint32_t*)(g_aBF + (size_t)r0*64);
        const uint32_t* a1 = (const uint32_t*)(g_aBF + (size_t)(r0+8)*64);
#pragma unroll
        for(int kt=0;kt<4;kt++){
            A[kt][0]=a0[kt*8+tg];   A[kt][1]=a1[kt*8+tg];
            A[kt][2]=a0[kt*8+tg+4]; A[kt][3]=a1[kt*8+tg+4];
        }
    }

    float Z[2]={0.f,0.f}, T1[2]={0.f,0.f}, T2[2]={0.f,0.f}, T3[2]={0.f,0.f}, MN[2]={1e30f,1e30f};

    {
        int jv0 = nvalid; if (jv0 > 128) jv0 = 128;
        stage_tile(0, jstart, jv0, adj, rt, smbase, tid);
    }

    for(int t=0;t<ntiles;t++){
        int j0 = jstart + (t<<7);
        int jv = NJ - j0; if (jv > 128) jv = 128;
        bool hasNext = (t+1) < ntiles;
        if (hasNext){
            int j1 = j0 + 128;
            int jv1 = NJ - j1; if (jv1 > 128) jv1 = 128;
            stage_tile((t+1)&1, j1, jv1, adj, rt, smbase, tid);
            asm volatile("cp.async.wait_group 1;" ::: "memory");
        } else {
            asm volatile("cp.async.wait_group 0;" ::: "memory");
        }
        __syncthreads();

        const char*  Es    = sm3 + (t&1)*ES_BYTES;
        const float* sadjB = (const float*)(sm3 + 2*ES_BYTES + (t&1)*ADJ_BYTES);

        float acc[16][4];
#pragma unroll
        for(int nt=0;nt<16;nt++){ acc[nt][0]=0.f; acc[nt][1]=0.f; acc[nt][2]=0.f; acc[nt][3]=0.f; }

#pragma unroll
        for(int kt=0;kt<4;kt++){
#pragma unroll
            for(int nt=0;nt<16;nt++){
                const char* bp = Es + (nt*8+g)*ES_STRIDE + kt*32 + tg*4;
                uint32_t b0 = *(const uint32_t*)bp;
                uint32_t b1 = *(const uint32_t*)(bp + 16);
                mma16816(acc[nt], A[kt], b0, b1);
            }
        }

        int r0l = wid*16 + g;
        if (jv == 128){
#pragma unroll
            for(int nt=0;nt<16;nt++){
                int c0 = nt*8 + tg*2;
                float2 ya = *(const float2*)(sadjB + r0l*ADJ_PITCH + c0);
                float2 yb = *(const float2*)(sadjB + (r0l+8)*ADJ_PITCH + c0);
                upd(acc[nt][0], ya.x, Z[0],T1[0],T2[0],T3[0],MN[0]);
                upd(acc[nt][1], ya.y, Z[0],T1[0],T2[0],T3[0],MN[0]);
                upd(acc[nt][2], yb.x, Z[1],T1[1],T2[1],T3[1],MN[1]);
                upd(acc[nt][3], yb.y, Z[1],T1[1],T2[1],T3[1],MN[1]);
            }
        } else {
#pragma unroll
            for(int nt=0;nt<16;nt++){
                int c0 = nt*8 + tg*2;
                if (c0 < jv){
                    float2 ya = *(const float2*)(sadjB + r0l*ADJ_PITCH + c0);
                    float2 yb = *(const float2*)(sadjB + (r0l+8)*ADJ_PITCH + c0);
                    upd(acc[nt][0], ya.x, Z[0],T1[0],T2[0],T3[0],MN[0]);
                    upd(acc[nt][2], yb.x, Z[1],T1[1],T2[1],T3[1],MN[1]);
                    if (c0 + 1 < jv){
                        upd(acc[nt][1], ya.y, Z[0],T1[0],T2[0],T3[0],MN[0]);
                        upd(acc[nt][3], yb.y, Z[1],T1[1],T2[1],T3[1],MN[1]);
                    }
                }
            }
        }
        __syncthreads();
    }

    // reduce over the 4 tg lanes (lane bits 0-1), write partials
#pragma unroll
    for(int r=0;r<2;r++){
#pragma unroll
        for(int off=1; off<4; off<<=1){
            Z[r]  += __shfl_xor_sync(0xffffffffu, Z[r],  off);
            T1[r] += __shfl_xor_sync(0xffffffffu, T1[r], off);
            T2[r] += __shfl_xor_sync(0xffffffffu, T2[r], off);
            T3[r] += __shfl_xor_sync(0xffffffffu, T3[r], off);
            MN[r]  = fminf(MN[r], __shfl_xor_sync(0xffffffffu, MN[r], off));
        }
    }
    if (tg == 0){
#pragma unroll
        for(int r=0;r<2;r++){
            int row = rt*128 + wid*16 + g + r*8;
            int o = jt*B + row;
            g_pz[o]=Z[r]; g_pt1[o]=T1[r]; g_pt2[o]=T2[r]; g_pt3[o]=T3[r]; g_ps[o]=MN[r];
        }
    }
}

// ---------------- kernel 4: parallel per-row merge ----------------
__global__ void k_rowred(){
    int b = blockIdx.x*128 + threadIdx.x;
    float Z=0.f, T1=0.f, T2=0.f, T3=0.f, S=1e30f;
#pragma unroll
    for(int jt=0;jt<JT;jt++){
        int o = jt*B + b;
        Z += g_pz[o]; T1 += g_pt1[o]; T2 += g_pt2[o]; T3 += g_pt3[o];
        S = fminf(S, g_ps[o]);
    }
    float lse2 = lg2f_(Z);
    g_lse2[b] = lse2;
    g_t3v[b]  = T3;
    g_cross[b] = T1 - lse2*T2;
    g_flag[b] = ((S - lse2) < LG2_EPS) ? 1 : 0;
}

// ---------------- kernel 5: exact clipped recompute (cold path) ----------------
__global__ void k_fixup(const float* __restrict__ adj){
    int b = blockIdx.x;
    if (!g_flag[b]) return;
    __shared__ float a[64];
    __shared__ float red[256];
    int t = threadIdx.x;
    if (t < 64) a[t] = __bfloat162float(g_aBF[b*64 + t]);
    __syncthreads();
    float lse2 = g_lse2[b];
    float cr = 0.f;
    for(int j=t; j<NJ; j+=256){
        float L = 0.f;
#pragma unroll
        for(int k=0;k<64;k++) L = fmaf(a[k], __bfloat162float(g_eB[(size_t)j*64 + k]), L);
        float y = fminf(fmaxf(adj[(size_t)b*NJ + j], KL_EPS), 1.f);
        cr = fmaf(y, fmaxf(L - lse2, LG2_EPS), cr);
    }
    red[t] = cr; __syncthreads();
    for(int s=128;s;s>>=1){ if (t < s) red[t] += red[t+s]; __syncthreads(); }
    if (t == 0) g_cross[b] = red[0];
}

// ---------------- kernel 6: final loss ----------------
__global__ void k_loss(const float* __restrict__ temp, float* __restrict__ out){
    __shared__ float red[B];
    int t = threadIdx.x;
    red[t] = g_t3v[t] - g_cross[t];
    __syncthreads();
    for(int s=512;s;s>>=1){ if (t < s) red[t] += red[t+s]; __syncthreads(); }
    if (t == 0){
        float T = temp[0];
        out[0] = red[0]*(1.0f/(float)B) + T*T*0.01f;
    }
}

// ---------------- launch ----------------
extern "C" void kernel_launch(void* const* d_in, const int* in_sizes, int n_in,
                              void* d_out, int out_size){
    const int*   cards = (const int*)  d_in[0];
    const float* adj   = (const float*)d_in[1];
    const float* emb   = (const float*)d_in[2];
    const float* W1    = (const float*)d_in[3];
    const float* b1    = (const float*)d_in[4];
    const float* W2    = (const float*)d_in[5];
    const float* b2    = (const float*)d_in[6];
    const float* temp  = (const float*)d_in[7];

    cudaFuncSetAttribute(k_mlp,   cudaFuncAttributeMaxDynamicSharedMemorySize, 155712);
    cudaFuncSetAttribute(k_gemm3, cudaFuncAttributeMaxDynamicSharedMemorySize, SMEM_TOTAL3);

    k_enorm<<<NJ_PAD/8, 256>>>(emb);
    k_mlp<<<64, 256, 155712>>>(cards, emb, W1, b1, W2, b2, temp);
    k_gemm3<<<dim3(JT, 8), 256, SMEM_TOTAL3>>>(adj);
    k_rowred<<<8, 128>>>();
    k_fixup<<<B, 256>>>(adj);
    k_loss<<<1, B>>>(temp, (float*)d_out);
}